// round 2
// baseline (speedup 1.0000x reference)
#include <cuda_runtime.h>
#include <math.h>

// Problem constants
#define BB 8
#define LL 2048
#define HH 768

// GEMM tiling
#define BM 128
#define BN 128
#define BK 8
#define TM 8
#define TN 8

// Scratch (static device memory — allocation-free per harness rules)
__device__ float g_S[(long)BB * LL * LL];        // attention scores / attn   (134 MB)
__device__ float g_P[3L * BB * LL * HH];         // HL | HS | HR              (151 MB)
__device__ float g_ctx[(long)BB * LL * HH];      // ctx before LN             (50 MB)

// ---------------------------------------------------------------------------
// Generic tiled SGEMM.
//   C[i,j] (+)= alpha * sum_k mask(A[i,k]) * B(k,j)   (+ bias[j])
// A: M x K row-major (lda).
// BT=true : B is N x K row-major (ldb=K stride) -> C = A * B^T
// BT=false: B is K x N row-major (ldb=N stride) -> C = A * B
// MODE: 0 none; 1 keep A[l,m] only if m > l (strict upper); 2 only if m < l.
// For MODE 1/2 the K loop is trimmed to the non-zero band.
// ---------------------------------------------------------------------------
template <int MODE, bool BT>
__global__ __launch_bounds__(256, 2)
void sgemm_kernel(const float* __restrict__ A, const float* __restrict__ B,
                  const float* __restrict__ bias, float* __restrict__ C,
                  int M, int N, int K, int lda, int ldb, int ldc,
                  long sA, long sB, long sC, float alpha, int accumulate)
{
    A += (long)blockIdx.z * sA;
    B += (long)blockIdx.z * sB;
    C += (long)blockIdx.z * sC;

    __shared__ float As[BK][BM];
    __shared__ float Bs[BK][BN];

    const int l0 = blockIdx.y * BM;
    const int n0 = blockIdx.x * BN;

    int kstart = 0, kend = K;
    if (MODE == 1) kstart = l0;                 // strict upper: m > l >= l0
    if (MODE == 2) kend = min(K, l0 + BM);      // strict lower: m < l < l0+BM

    const int t = threadIdx.x;
    const int arow = t >> 1;
    const int acol = (t & 1) * 4;
    const int brow = t >> 1;           // BT layout
    const int bcol = (t & 1) * 4;      // BT layout
    const int bk   = t >> 5;           // NN layout
    const int bn   = (t & 31) * 4;     // NN layout

    const int ty = t >> 4;   // 0..15
    const int tx = t & 15;   // 0..15

    float acc[TM][TN];
#pragma unroll
    for (int i = 0; i < TM; i++)
#pragma unroll
        for (int j = 0; j < TN; j++) acc[i][j] = 0.f;

    for (int kt = kstart; kt < kend; kt += BK) {
        // --- load A tile (BM x BK), apply mask + alpha, store transposed ---
        const int lg = l0 + arow;
        float4 av = *(const float4*)(A + (long)lg * lda + kt + acol);
        float a0 = av.x * alpha, a1 = av.y * alpha, a2 = av.z * alpha, a3 = av.w * alpha;
        if (MODE == 1) {
            const int mg = kt + acol;
            if (!(mg + 0 > lg)) a0 = 0.f;
            if (!(mg + 1 > lg)) a1 = 0.f;
            if (!(mg + 2 > lg)) a2 = 0.f;
            if (!(mg + 3 > lg)) a3 = 0.f;
        } else if (MODE == 2) {
            const int mg = kt + acol;
            if (!(mg + 0 < lg)) a0 = 0.f;
            if (!(mg + 1 < lg)) a1 = 0.f;
            if (!(mg + 2 < lg)) a2 = 0.f;
            if (!(mg + 3 < lg)) a3 = 0.f;
        }
        As[acol + 0][arow] = a0;
        As[acol + 1][arow] = a1;
        As[acol + 2][arow] = a2;
        As[acol + 3][arow] = a3;

        // --- load B tile ---
        if (BT) {
            float4 bv = *(const float4*)(B + (long)(n0 + brow) * ldb + kt + bcol);
            Bs[bcol + 0][brow] = bv.x;
            Bs[bcol + 1][brow] = bv.y;
            Bs[bcol + 2][brow] = bv.z;
            Bs[bcol + 3][brow] = bv.w;
        } else {
            float4 bv = *(const float4*)(B + (long)(kt + bk) * ldb + n0 + bn);
            *(float4*)&Bs[bk][bn] = bv;
        }
        __syncthreads();

        // --- compute ---
#pragma unroll
        for (int k = 0; k < BK; k++) {
            float ra[TM], rb[TN];
            float4 va0 = *(const float4*)&As[k][ty * TM + 0];
            float4 va1 = *(const float4*)&As[k][ty * TM + 4];
            ra[0] = va0.x; ra[1] = va0.y; ra[2] = va0.z; ra[3] = va0.w;
            ra[4] = va1.x; ra[5] = va1.y; ra[6] = va1.z; ra[7] = va1.w;
            float4 vb0 = *(const float4*)&Bs[k][tx * TN + 0];
            float4 vb1 = *(const float4*)&Bs[k][tx * TN + 4];
            rb[0] = vb0.x; rb[1] = vb0.y; rb[2] = vb0.z; rb[3] = vb0.w;
            rb[4] = vb1.x; rb[5] = vb1.y; rb[6] = vb1.z; rb[7] = vb1.w;
#pragma unroll
            for (int i = 0; i < TM; i++)
#pragma unroll
                for (int j = 0; j < TN; j++)
                    acc[i][j] = fmaf(ra[i], rb[j], acc[i][j]);
        }
        __syncthreads();
    }

    // --- epilogue ---
#pragma unroll
    for (int i = 0; i < TM; i++) {
        const long crow = (long)(l0 + ty * TM + i) * ldc + n0 + tx * TN;
#pragma unroll
        for (int jj = 0; jj < 2; jj++) {
            float4 v;
            v.x = acc[i][jj * 4 + 0];
            v.y = acc[i][jj * 4 + 1];
            v.z = acc[i][jj * 4 + 2];
            v.w = acc[i][jj * 4 + 3];
            if (bias) {
                float4 bv = *(const float4*)(bias + n0 + tx * TN + jj * 4);
                v.x += bv.x; v.y += bv.y; v.z += bv.z; v.w += bv.w;
            }
            if (accumulate) {
                float4 cv = *(const float4*)(C + crow + jj * 4);
                v.x += cv.x; v.y += cv.y; v.z += cv.z; v.w += cv.w;
            }
            *(float4*)(C + crow + jj * 4) = v;
        }
    }
}

// ---------------------------------------------------------------------------
// Block reductions (256 threads)
// ---------------------------------------------------------------------------
template <bool MAXOP>
__device__ __forceinline__ float block_reduce_256(float v)
{
    __shared__ float sm[8];
#pragma unroll
    for (int o = 16; o > 0; o >>= 1) {
        float w = __shfl_xor_sync(0xffffffffu, v, o);
        v = MAXOP ? fmaxf(v, w) : (v + w);
    }
    __syncthreads();   // protect sm reuse across successive calls
    if ((threadIdx.x & 31) == 0) sm[threadIdx.x >> 5] = v;
    __syncthreads();
    v = sm[threadIdx.x & 7];
#pragma unroll
    for (int o = 4; o > 0; o >>= 1) {
        float w = __shfl_xor_sync(0xffffffffu, v, o);
        v = MAXOP ? fmaxf(v, w) : (v + w);
    }
    return v;
}

// ---------------------------------------------------------------------------
// Row softmax + adjacency renorm (in place on S).
//   p = softmax(u); delta = p*adj; attn = delta / (sum(delta) + 1e-10)
// which equals  e*adj / (T + 1e-10*Z)  with e = exp(u - max), Z = sum e,
// T = sum e*adj.  Exact (Z does not cancel from the +1e-10 term).
// ---------------------------------------------------------------------------
__global__ __launch_bounds__(256)
void softmax_adj_kernel(float* __restrict__ S, const float* __restrict__ adj)
{
    const long base = (long)blockIdx.x * LL;
    const int t = threadIdx.x;

    float x[8], a[8];
#pragma unroll
    for (int i = 0; i < 8; i++) x[i] = S[base + t + i * 256];
#pragma unroll
    for (int i = 0; i < 8; i++) a[i] = adj[base + t + i * 256];

    float m = -INFINITY;
#pragma unroll
    for (int i = 0; i < 8; i++) m = fmaxf(m, x[i]);
    m = block_reduce_256<true>(m);

    float e[8];
    float z = 0.f, tt = 0.f;
#pragma unroll
    for (int i = 0; i < 8; i++) {
        e[i] = __expf(x[i] - m);
        z += e[i];
        tt += e[i] * a[i];
    }
    z  = block_reduce_256<false>(z);
    tt = block_reduce_256<false>(tt);

    const float inv = 1.0f / (tt + 1e-10f * z);
#pragma unroll
    for (int i = 0; i < 8; i++)
        S[base + t + i * 256] = e[i] * a[i] * inv;
}

// ---------------------------------------------------------------------------
// Fused: v = ctx + attn[l,l]*h_self ; LayerNorm(eps=1e-12); ReLU
// One block per (b,l) row, 256 threads x 3 elements.
// ---------------------------------------------------------------------------
__global__ __launch_bounds__(256)
void ln_relu_kernel(const float* __restrict__ ctx, const float* __restrict__ HS,
                    const float* __restrict__ S, const float* __restrict__ gamma,
                    const float* __restrict__ beta, float* __restrict__ out)
{
    const int row = blockIdx.x;            // b*L + l
    const int l = row & (LL - 1);
    const float a_ll = S[(long)row * LL + l];
    const long rb = (long)row * HH;
    const int t = threadIdx.x;

    float v[3];
#pragma unroll
    for (int i = 0; i < 3; i++) {
        const int c = t + i * 256;
        v[i] = ctx[rb + c] + a_ll * HS[rb + c];
    }
    float s = v[0] + v[1] + v[2];
    s = block_reduce_256<false>(s);
    const float mu = s * (1.0f / HH);

    float sq = 0.f;
#pragma unroll
    for (int i = 0; i < 3; i++) {
        const float d = v[i] - mu;
        sq += d * d;
    }
    sq = block_reduce_256<false>(sq);
    const float rstd = rsqrtf(sq * (1.0f / HH) + 1e-12f);

#pragma unroll
    for (int i = 0; i < 3; i++) {
        const int c = t + i * 256;
        const float o = (v[i] - mu) * rstd * gamma[c] + beta[c];
        out[rb + c] = fmaxf(o, 0.f);
    }
}

// ---------------------------------------------------------------------------
extern "C" void kernel_launch(void* const* d_in, const int* in_sizes, int n_in,
                              void* d_out, int out_size)
{
    const float* h     = (const float*)d_in[0];
    const float* adj   = (const float*)d_in[1];
    const float* Wl    = (const float*)d_in[2];
    const float* bl    = (const float*)d_in[3];
    const float* Ws    = (const float*)d_in[4];
    const float* bs    = (const float*)d_in[5];
    const float* Wr    = (const float*)d_in[6];
    const float* br    = (const float*)d_in[7];
    const float* gamma = (const float*)d_in[8];
    const float* beta  = (const float*)d_in[9];
    float* out = (float*)d_out;

    float *S, *P, *CTX;
    cudaGetSymbolAddress((void**)&S, g_S);
    cudaGetSymbolAddress((void**)&P, g_P);
    cudaGetSymbolAddress((void**)&CTX, g_ctx);

    const long sLH = (long)LL * HH;     // per-batch h / proj stride
    const long sLL = (long)LL * LL;     // per-batch attn stride
    const long BLH = (long)BB * sLH;    // full projection buffer stride

    const float inv_sqrt_h = 1.0f / sqrtf((float)HH);

    // 1) S = h @ h^T / sqrt(H)   (NT, batched)
    {
        dim3 grid(LL / BN, LL / BM, BB);
        sgemm_kernel<0, true><<<grid, 256>>>(h, h, nullptr, S,
                                             LL, LL, HH, HH, HH, LL,
                                             sLH, sLH, sLL, inv_sqrt_h, 0);
    }

    // 2) softmax + adjacency renorm (in place)
    softmax_adj_kernel<<<BB * LL, 256>>>(S, adj);

    // 3) three projections: P_x = h @ W_x^T + b_x   (NT, M = B*L)
    {
        dim3 grid(HH / BN, (BB * LL) / BM, 1);
        sgemm_kernel<0, true><<<grid, 256>>>(h, Wl, bl, P + 0 * BLH,
                                             BB * LL, HH, HH, HH, HH, HH,
                                             0, 0, 0, 1.f, 0);
        sgemm_kernel<0, true><<<grid, 256>>>(h, Ws, bs, P + 1 * BLH,
                                             BB * LL, HH, HH, HH, HH, HH,
                                             0, 0, 0, 1.f, 0);
        sgemm_kernel<0, true><<<grid, 256>>>(h, Wr, br, P + 2 * BLH,
                                             BB * LL, HH, HH, HH, HH, HH,
                                             0, 0, 0, 1.f, 0);
    }

    // 4) ctx = triu(attn,1) @ HL  +  tril(attn,-1) @ HR   (NN, batched, banded K)
    {
        dim3 grid(HH / BN, LL / BM, BB);
        sgemm_kernel<1, false><<<grid, 256>>>(S, P + 0 * BLH, nullptr, CTX,
                                              LL, HH, LL, LL, HH, HH,
                                              sLL, sLH, sLH, 1.f, 0);
        sgemm_kernel<2, false><<<grid, 256>>>(S, P + 2 * BLH, nullptr, CTX,
                                              LL, HH, LL, LL, HH, HH,
                                              sLL, sLH, sLH, 1.f, 1);
    }

    // 5) + diag(attn)*h_self, LayerNorm, ReLU
    ln_relu_kernel<<<BB * LL, 256>>>(CTX, P + 1 * BLH, S, gamma, beta, out);
}

// round 3
// speedup vs baseline: 2.1529x; 2.1529x over previous
#include <cuda_runtime.h>
#include <cuda_bf16.h>
#include <math.h>
#include <stdint.h>

// Problem constants
#define BB 8
#define LL 2048
#define HH 768

typedef __nv_bfloat16 bf16;

// ---------------------------------------------------------------------------
// Static scratch (allocation-free per harness rules)
// ---------------------------------------------------------------------------
__device__ float g_S   [(long)BB * LL * LL];     // fp32 scores           134MB
__device__ bf16  g_Shi [(long)BB * LL * LL];     // attn hi                67MB
__device__ bf16  g_Slo [(long)BB * LL * LL];     // attn lo                67MB
__device__ bf16  g_hhi [(long)BB * LL * HH];     // h hi                   25MB
__device__ bf16  g_hlo [(long)BB * LL * HH];
__device__ bf16  g_Whi [3L * HH * HH];           // Wl|Ws|Wr hi
__device__ bf16  g_Wlo [3L * HH * HH];
__device__ bf16  g_PLhi[(long)BB * LL * HH];     // h_left  pair
__device__ bf16  g_PLlo[(long)BB * LL * HH];
__device__ bf16  g_PRhi[(long)BB * LL * HH];     // h_right pair
__device__ bf16  g_PRlo[(long)BB * LL * HH];
__device__ float g_Pself[(long)BB * LL * HH];    // h_self fp32            50MB
__device__ float g_ctx [(long)BB * LL * HH];     // ctx fp32               50MB
__device__ float g_diag[(long)BB * LL];          // diag(attn) fp32

// ---------------------------------------------------------------------------
// Helpers
// ---------------------------------------------------------------------------
__device__ __forceinline__ void split_f32(float x, bf16& hi, bf16& lo)
{
    hi = __float2bfloat16(x);
    lo = __float2bfloat16(x - __bfloat162float(hi));
}

__device__ __forceinline__ void ldsm4(uint32_t& d0, uint32_t& d1, uint32_t& d2,
                                      uint32_t& d3, const bf16* p)
{
    uint32_t a = (uint32_t)__cvta_generic_to_shared(p);
    asm volatile("ldmatrix.sync.aligned.m8n8.x4.shared.b16 {%0,%1,%2,%3}, [%4];"
                 : "=r"(d0), "=r"(d1), "=r"(d2), "=r"(d3) : "r"(a));
}

__device__ __forceinline__ void ldsm4t(uint32_t& d0, uint32_t& d1, uint32_t& d2,
                                       uint32_t& d3, const bf16* p)
{
    uint32_t a = (uint32_t)__cvta_generic_to_shared(p);
    asm volatile("ldmatrix.sync.aligned.m8n8.x4.trans.shared.b16 {%0,%1,%2,%3}, [%4];"
                 : "=r"(d0), "=r"(d1), "=r"(d2), "=r"(d3) : "r"(a));
}

__device__ __forceinline__ void mma16816(float* c, const uint32_t* a,
                                         uint32_t b0, uint32_t b1)
{
    asm volatile(
        "mma.sync.aligned.m16n8k16.row.col.f32.bf16.bf16.f32 "
        "{%0,%1,%2,%3}, {%4,%5,%6,%7}, {%8,%9}, {%0,%1,%2,%3};"
        : "+f"(c[0]), "+f"(c[1]), "+f"(c[2]), "+f"(c[3])
        : "r"(a[0]), "r"(a[1]), "r"(a[2]), "r"(a[3]), "r"(b0), "r"(b1));
}

// ---------------------------------------------------------------------------
// bf16-pair tensor-core GEMM with fp32 accumulation.
//   C = alpha * (Ahi+Alo)(Bhi+Blo)^(T?)  (+bias) (+C)
// computed as Ahi*Bhi + Ahi*Blo + Alo*Bhi  (lo*lo dropped).
// A: M x K row-major. BT=true: B is N x K row-major (C=A*B^T).
//                     BT=false: B is K x N row-major (C=A*B).
// MODE 0 none; 1 keep A[l,m] iff m>l; 2 iff m<l (K-loop trimmed to band).
// EPI 0: fp32 out (alpha, optional bias, optional accumulate)
// EPI 1: bf16 hi/lo pair out (bias required)
// CTA tile 128x128, 8 warps (2x4), warp tile 64x32, k-tile 32.
// ---------------------------------------------------------------------------
template <int MODE, bool BT, int EPI>
__global__ __launch_bounds__(256)
void mma_gemm(const bf16* __restrict__ Ahi, const bf16* __restrict__ Alo,
              const bf16* __restrict__ Bhi, const bf16* __restrict__ Blo,
              const float* __restrict__ bias,
              float* __restrict__ Cf, bf16* __restrict__ Chi, bf16* __restrict__ Clo,
              int M, int N, int K, int lda, int ldb, int ldc,
              long sA, long sB, long sC, float alpha, int accumulate)
{
    Ahi += (long)blockIdx.z * sA;  Alo += (long)blockIdx.z * sA;
    Bhi += (long)blockIdx.z * sB;  Blo += (long)blockIdx.z * sB;
    if (EPI == 0) Cf += (long)blockIdx.z * sC;
    else { Chi += (long)blockIdx.z * sC; Clo += (long)blockIdx.z * sC; }

    // smem tiles: A 128x32 (stride 40), B NT 128x32 (stride 40), B NN 32x128 (stride 136)
    __shared__ __align__(16) bf16 sAh[128 * 40];
    __shared__ __align__(16) bf16 sAl[128 * 40];
    __shared__ __align__(16) bf16 sBh[128 * 40];
    __shared__ __align__(16) bf16 sBl[128 * 40];

    const int l0 = blockIdx.y * 128;
    const int n0 = blockIdx.x * 128;
    const int t = threadIdx.x;
    const int warp = t >> 5;
    const int lane = t & 31;
    const int wm = warp >> 2;        // 0..1  -> m offset wm*64
    const int wn = warp & 3;         // 0..3  -> n offset wn*32

    int kstart = 0, kend = K;
    if (MODE == 1) kstart = l0;
    if (MODE == 2) kend = min(K, l0 + 128);

    float acc[4][4][4];
#pragma unroll
    for (int i = 0; i < 4; i++)
#pragma unroll
        for (int j = 0; j < 4; j++)
#pragma unroll
            for (int r = 0; r < 4; r++) acc[i][j][r] = 0.f;

    for (int kt = kstart; kt < kend; kt += 32) {
        __syncthreads();
        const bool interior = (MODE == 0) ||
                              (MODE == 1 ? (kt >= l0 + 128) : (kt + 32 <= l0));
        // ---- A tile: 128x32, chunk = 8 bf16 ----
#pragma unroll
        for (int it = 0; it < 2; it++) {
            const int idx = t * 2 + it;              // 0..511
            const int r = idx >> 2;
            const int c8 = (idx & 3) << 3;
            const long go = (long)(l0 + r) * lda + kt + c8;
            if (interior) {
                *(uint4*)&sAh[r * 40 + c8] = *(const uint4*)(Ahi + go);
                *(uint4*)&sAl[r * 40 + c8] = *(const uint4*)(Alo + go);
            } else {
                const int l = l0 + r;
#pragma unroll
                for (int e = 0; e < 8; e++) {
                    const int m = kt + c8 + e;
                    const bool keep = (MODE == 1) ? (m > l) : (m < l);
                    sAh[r * 40 + c8 + e] = keep ? Ahi[go + e] : __float2bfloat16(0.f);
                    sAl[r * 40 + c8 + e] = keep ? Alo[go + e] : __float2bfloat16(0.f);
                }
            }
        }
        // ---- B tile ----
#pragma unroll
        for (int it = 0; it < 2; it++) {
            const int idx = t * 2 + it;
            if (BT) {   // [n][k] 128x32
                const int r = idx >> 2;
                const int c8 = (idx & 3) << 3;
                const long go = (long)(n0 + r) * ldb + kt + c8;
                *(uint4*)&sBh[r * 40 + c8] = *(const uint4*)(Bhi + go);
                *(uint4*)&sBl[r * 40 + c8] = *(const uint4*)(Blo + go);
            } else {    // [k][n] 32x128
                const int r = idx >> 4;
                const int c8 = (idx & 15) << 3;
                const long go = (long)(kt + r) * ldb + n0 + c8;
                *(uint4*)&sBh[r * 136 + c8] = *(const uint4*)(Bhi + go);
                *(uint4*)&sBl[r * 136 + c8] = *(const uint4*)(Blo + go);
            }
        }
        __syncthreads();

        // ---- compute: two k16 halves ----
#pragma unroll
        for (int kk = 0; kk < 2; kk++) {
            uint32_t ah[4][4], al[4][4], bh[2][4], bl[2][4];
            const int arow = wm * 64 + (lane & 15);
            const int acol = kk * 16 + ((lane >> 4) << 3);
#pragma unroll
            for (int mi = 0; mi < 4; mi++) {
                const bf16* pa = &sAh[(arow + mi * 16) * 40 + acol];
                ldsm4(ah[mi][0], ah[mi][1], ah[mi][2], ah[mi][3], pa);
                const bf16* pl = &sAl[(arow + mi * 16) * 40 + acol];
                ldsm4(al[mi][0], al[mi][1], al[mi][2], al[mi][3], pl);
            }
            if (BT) {
                const int brow = wn * 32 + (lane & 15);
#pragma unroll
                for (int ni = 0; ni < 2; ni++) {
                    ldsm4(bh[ni][0], bh[ni][1], bh[ni][2], bh[ni][3],
                          &sBh[(brow + ni * 16) * 40 + acol]);
                    ldsm4(bl[ni][0], bl[ni][1], bl[ni][2], bl[ni][3],
                          &sBl[(brow + ni * 16) * 40 + acol]);
                }
            } else {
                const int krow = kk * 16 + (lane & 7) + ((lane >> 4) & 1) * 8;
                const int nc = wn * 32 + ((lane >> 3) & 1) * 8;
#pragma unroll
                for (int ni = 0; ni < 2; ni++) {
                    ldsm4t(bh[ni][0], bh[ni][1], bh[ni][2], bh[ni][3],
                           &sBh[krow * 136 + nc + ni * 16]);
                    ldsm4t(bl[ni][0], bl[ni][1], bl[ni][2], bl[ni][3],
                           &sBl[krow * 136 + nc + ni * 16]);
                }
            }
#pragma unroll
            for (int mi = 0; mi < 4; mi++)
#pragma unroll
                for (int j = 0; j < 4; j++) {
                    const int ni = j >> 1, hf = j & 1;
                    mma16816(acc[mi][j], ah[mi], bh[ni][hf], bh[ni][hf + 2]);
                    mma16816(acc[mi][j], ah[mi], bl[ni][hf], bl[ni][hf + 2]);
                    mma16816(acc[mi][j], al[mi], bh[ni][hf], bh[ni][hf + 2]);
                }
        }
    }

    // ---- epilogue ----
    const int g = lane >> 2, tg = lane & 3;
#pragma unroll
    for (int mi = 0; mi < 4; mi++) {
#pragma unroll
        for (int j = 0; j < 4; j++) {
            const int gn = n0 + wn * 32 + j * 8 + tg * 2;
            const float* a = acc[mi][j];
#pragma unroll
            for (int h2 = 0; h2 < 2; h2++) {
                const int gm = l0 + wm * 64 + mi * 16 + g + h2 * 8;
                float v0 = a[h2 * 2 + 0] * alpha;
                float v1 = a[h2 * 2 + 1] * alpha;
                if (EPI == 0) {
                    if (bias) { v0 += bias[gn]; v1 += bias[gn + 1]; }
                    float2* p = (float2*)(Cf + (long)gm * ldc + gn);
                    if (accumulate) { float2 o = *p; v0 += o.x; v1 += o.y; }
                    *p = make_float2(v0, v1);
                } else {
                    v0 += bias[gn]; v1 += bias[gn + 1];
                    bf16 h0, lo0, h1, lo1;
                    split_f32(v0, h0, lo0);
                    split_f32(v1, h1, lo1);
                    *(__nv_bfloat162*)(Chi + (long)gm * ldc + gn) =
                        __halves2bfloat162(h0, h1);
                    *(__nv_bfloat162*)(Clo + (long)gm * ldc + gn) =
                        __halves2bfloat162(lo0, lo1);
                }
            }
        }
    }
}

// ---------------------------------------------------------------------------
// fp32 -> bf16 hi/lo split (vectorized by 4)
// ---------------------------------------------------------------------------
__global__ __launch_bounds__(256)
void split4_kernel(const float* __restrict__ x, bf16* __restrict__ hi,
                   bf16* __restrict__ lo, long n4)
{
    const long i = (long)blockIdx.x * blockDim.x + threadIdx.x;
    if (i >= n4) return;
    float4 v = ((const float4*)x)[i];
    bf16 h0, l0, h1, l1, h2, l2, h3, l3;
    split_f32(v.x, h0, l0); split_f32(v.y, h1, l1);
    split_f32(v.z, h2, l2); split_f32(v.w, h3, l3);
    ((__nv_bfloat162*)hi)[i * 2 + 0] = __halves2bfloat162(h0, h1);
    ((__nv_bfloat162*)hi)[i * 2 + 1] = __halves2bfloat162(h2, h3);
    ((__nv_bfloat162*)lo)[i * 2 + 0] = __halves2bfloat162(l0, l1);
    ((__nv_bfloat162*)lo)[i * 2 + 1] = __halves2bfloat162(l2, l3);
}

// ---------------------------------------------------------------------------
// Block reductions (256 threads)
// ---------------------------------------------------------------------------
template <bool MAXOP>
__device__ __forceinline__ float block_reduce_256(float v)
{
    __shared__ float sm[8];
#pragma unroll
    for (int o = 16; o > 0; o >>= 1) {
        float w = __shfl_xor_sync(0xffffffffu, v, o);
        v = MAXOP ? fmaxf(v, w) : (v + w);
    }
    __syncthreads();
    if ((threadIdx.x & 31) == 0) sm[threadIdx.x >> 5] = v;
    __syncthreads();
    v = sm[threadIdx.x & 7];
#pragma unroll
    for (int o = 4; o > 0; o >>= 1) {
        float w = __shfl_xor_sync(0xffffffffu, v, o);
        v = MAXOP ? fmaxf(v, w) : (v + w);
    }
    return v;
}

// ---------------------------------------------------------------------------
// softmax + adjacency renorm:  attn = e*adj / (T + 1e-10*Z).
// Writes attn as bf16 hi/lo pair + fp32 diagonal.
// ---------------------------------------------------------------------------
__global__ __launch_bounds__(256)
void softmax_adj_kernel(const float* __restrict__ S, const float* __restrict__ adj,
                        bf16* __restrict__ Shi, bf16* __restrict__ Slo,
                        float* __restrict__ diag)
{
    const int row = blockIdx.x;              // b*L + l
    const int l = row & (LL - 1);
    const long base = (long)row * LL;
    const int t = threadIdx.x;

    float x[8], a[8];
#pragma unroll
    for (int i = 0; i < 8; i++) x[i] = S[base + t + i * 256];
#pragma unroll
    for (int i = 0; i < 8; i++) a[i] = adj[base + t + i * 256];

    float m = -INFINITY;
#pragma unroll
    for (int i = 0; i < 8; i++) m = fmaxf(m, x[i]);
    m = block_reduce_256<true>(m);

    float e[8];
    float z = 0.f, tt = 0.f;
#pragma unroll
    for (int i = 0; i < 8; i++) {
        e[i] = __expf(x[i] - m);
        z += e[i];
        tt += e[i] * a[i];
    }
    z  = block_reduce_256<false>(z);
    tt = block_reduce_256<false>(tt);

    const float inv = 1.0f / (tt + 1e-10f * z);
#pragma unroll
    for (int i = 0; i < 8; i++) {
        const int col = t + i * 256;
        const float v = e[i] * a[i] * inv;
        bf16 hi, lo;
        split_f32(v, hi, lo);
        Shi[base + col] = hi;
        Slo[base + col] = lo;
        if (col == l) diag[row] = v;
    }
}

// ---------------------------------------------------------------------------
// Fused: v = ctx + diag*h_self ; LayerNorm(eps=1e-12); ReLU
// ---------------------------------------------------------------------------
__global__ __launch_bounds__(256)
void ln_relu_kernel(const float* __restrict__ ctx, const float* __restrict__ HS,
                    const float* __restrict__ diag, const float* __restrict__ gamma,
                    const float* __restrict__ beta, float* __restrict__ out)
{
    const int row = blockIdx.x;
    const float a_ll = diag[row];
    const long rb = (long)row * HH;
    const int t = threadIdx.x;

    float v[3];
#pragma unroll
    for (int i = 0; i < 3; i++) {
        const int c = t + i * 256;
        v[i] = ctx[rb + c] + a_ll * HS[rb + c];
    }
    float s = v[0] + v[1] + v[2];
    s = block_reduce_256<false>(s);
    const float mu = s * (1.0f / HH);

    float sq = 0.f;
#pragma unroll
    for (int i = 0; i < 3; i++) {
        const float d = v[i] - mu;
        sq += d * d;
    }
    sq = block_reduce_256<false>(sq);
    const float rstd = rsqrtf(sq * (1.0f / HH) + 1e-12f);

#pragma unroll
    for (int i = 0; i < 3; i++) {
        const int c = t + i * 256;
        const float o = (v[i] - mu) * rstd * gamma[c] + beta[c];
        out[rb + c] = fmaxf(o, 0.f);
    }
}

// ---------------------------------------------------------------------------
extern "C" void kernel_launch(void* const* d_in, const int* in_sizes, int n_in,
                              void* d_out, int out_size)
{
    const float* h     = (const float*)d_in[0];
    const float* adj   = (const float*)d_in[1];
    const float* Wl    = (const float*)d_in[2];
    const float* bl    = (const float*)d_in[3];
    const float* Ws    = (const float*)d_in[4];
    const float* bs    = (const float*)d_in[5];
    const float* Wr    = (const float*)d_in[6];
    const float* br    = (const float*)d_in[7];
    const float* gamma = (const float*)d_in[8];
    const float* beta  = (const float*)d_in[9];
    float* out = (float*)d_out;

    float *S, *Pself, *CTX, *DIAG;
    bf16 *Shi, *Slo, *hhi, *hlo, *Whi, *Wlo, *PLhi, *PLlo, *PRhi, *PRlo;
    cudaGetSymbolAddress((void**)&S, g_S);
    cudaGetSymbolAddress((void**)&Shi, g_Shi);
    cudaGetSymbolAddress((void**)&Slo, g_Slo);
    cudaGetSymbolAddress((void**)&hhi, g_hhi);
    cudaGetSymbolAddress((void**)&hlo, g_hlo);
    cudaGetSymbolAddress((void**)&Whi, g_Whi);
    cudaGetSymbolAddress((void**)&Wlo, g_Wlo);
    cudaGetSymbolAddress((void**)&PLhi, g_PLhi);
    cudaGetSymbolAddress((void**)&PLlo, g_PLlo);
    cudaGetSymbolAddress((void**)&PRhi, g_PRhi);
    cudaGetSymbolAddress((void**)&PRlo, g_PRlo);
    cudaGetSymbolAddress((void**)&Pself, g_Pself);
    cudaGetSymbolAddress((void**)&CTX, g_ctx);
    cudaGetSymbolAddress((void**)&DIAG, g_diag);

    const long sLH = (long)LL * HH;
    const long sLL = (long)LL * LL;
    const long WW = (long)HH * HH;
    const float inv_sqrt_h = 1.0f / sqrtf((float)HH);

    // 0) operand conversion
    {
        const long n4h = (long)BB * LL * HH / 4;
        split4_kernel<<<(int)((n4h + 255) / 256), 256>>>(h, hhi, hlo, n4h);
        const long n4w = WW / 4;
        split4_kernel<<<(int)((n4w + 255) / 256), 256>>>(Wl, Whi + 0 * WW, Wlo + 0 * WW, n4w);
        split4_kernel<<<(int)((n4w + 255) / 256), 256>>>(Ws, Whi + 1 * WW, Wlo + 1 * WW, n4w);
        split4_kernel<<<(int)((n4w + 255) / 256), 256>>>(Wr, Whi + 2 * WW, Wlo + 2 * WW, n4w);
    }

    // 1) S = h @ h^T / sqrt(H)  (NT, batched)
    {
        dim3 grid(LL / 128, LL / 128, BB);
        mma_gemm<0, true, 0><<<grid, 256>>>(hhi, hlo, hhi, hlo, nullptr,
                                            S, nullptr, nullptr,
                                            LL, LL, HH, HH, HH, LL,
                                            sLH, sLH, sLL, inv_sqrt_h, 0);
    }

    // 2) softmax + adjacency renorm -> attn (bf16 pair) + diag (fp32)
    softmax_adj_kernel<<<BB * LL, 256>>>(S, adj, Shi, Slo, DIAG);

    // 3) projections (NT, M = B*L)
    {
        dim3 grid(HH / 128, (BB * LL) / 128, 1);
        mma_gemm<0, true, 1><<<grid, 256>>>(hhi, hlo, Whi + 0 * WW, Wlo + 0 * WW, bl,
                                            nullptr, PLhi, PLlo,
                                            BB * LL, HH, HH, HH, HH, HH,
                                            0, 0, 0, 1.f, 0);
        mma_gemm<0, true, 0><<<grid, 256>>>(hhi, hlo, Whi + 1 * WW, Wlo + 1 * WW, bs,
                                            Pself, nullptr, nullptr,
                                            BB * LL, HH, HH, HH, HH, HH,
                                            0, 0, 0, 1.f, 0);
        mma_gemm<0, true, 1><<<grid, 256>>>(hhi, hlo, Whi + 2 * WW, Wlo + 2 * WW, br,
                                            nullptr, PRhi, PRlo,
                                            BB * LL, HH, HH, HH, HH, HH,
                                            0, 0, 0, 1.f, 0);
    }

    // 4) ctx = triu(attn,1) @ HL + tril(attn,-1) @ HR  (NN, batched, banded K)
    {
        dim3 grid(HH / 128, LL / 128, BB);
        mma_gemm<1, false, 0><<<grid, 256>>>(Shi, Slo, PLhi, PLlo, nullptr,
                                             CTX, nullptr, nullptr,
                                             LL, HH, LL, LL, HH, HH,
                                             sLL, sLH, sLH, 1.f, 0);
        mma_gemm<2, false, 0><<<grid, 256>>>(Shi, Slo, PRhi, PRlo, nullptr,
                                             CTX, nullptr, nullptr,
                                             LL, HH, LL, LL, HH, HH,
                                             sLL, sLH, sLH, 1.f, 1);
    }

    // 5) + diag*h_self, LayerNorm, ReLU
    ln_relu_kernel<<<BB * LL, 256>>>(CTX, Pself, DIAG, gamma, beta, out);
}

// round 8
// speedup vs baseline: 2.2559x; 1.0479x over previous
#include <cuda_runtime.h>
#include <cuda_bf16.h>
#include <math.h>
#include <stdint.h>

// Problem constants
#define BB 8
#define LL 2048
#define HH 768

typedef __nv_bfloat16 bf16;

// Tiling: CTA 128x128, 8 warps (2x4), warp 64x32, k-tile 32, 2-stage pipeline
#define BK 32
#define STG_B 40960          // bytes per pipeline stage (4 buffers x 10240)
#define OFF_AH 0
#define OFF_AL 10240
#define OFF_BH 20480
#define OFF_BL 30720
#define DSMEM_BYTES (2 * STG_B)

// ---------------------------------------------------------------------------
// Static scratch (allocation-free per harness rules)
// ---------------------------------------------------------------------------
__device__ float g_S   [(long)BB * LL * LL];     // fp32 scores
__device__ bf16  g_Shi [(long)BB * LL * LL];     // attn hi
__device__ bf16  g_Slo [(long)BB * LL * LL];     // attn lo
__device__ bf16  g_hhi [(long)BB * LL * HH];
__device__ bf16  g_hlo [(long)BB * LL * HH];
__device__ bf16  g_Whi [3L * HH * HH];
__device__ bf16  g_Wlo [3L * HH * HH];
__device__ bf16  g_PLhi[(long)BB * LL * HH];     // h_left  pair [bL][e]
__device__ bf16  g_PLlo[(long)BB * LL * HH];
__device__ bf16  g_PRhi[(long)BB * LL * HH];     // h_right pair
__device__ bf16  g_PRlo[(long)BB * LL * HH];
__device__ float g_Pself[(long)BB * LL * HH];    // h_self fp32
__device__ float g_ctx [(long)BB * LL * HH];
__device__ float g_diag[(long)BB * LL];

// ---------------------------------------------------------------------------
// Helpers
// ---------------------------------------------------------------------------
__device__ __forceinline__ void split_f32(float x, bf16& hi, bf16& lo)
{
    hi = __float2bfloat16(x);
    lo = __float2bfloat16(x - __bfloat162float(hi));
}

__device__ __forceinline__ void cpa16(uint32_t dst, const void* src)
{
    asm volatile("cp.async.cg.shared.global [%0], [%1], 16;" :: "r"(dst), "l"(src));
}

__device__ __forceinline__ void ldsm4(uint32_t& d0, uint32_t& d1, uint32_t& d2,
                                      uint32_t& d3, const bf16* p)
{
    uint32_t a = (uint32_t)__cvta_generic_to_shared(p);
    asm volatile("ldmatrix.sync.aligned.m8n8.x4.shared.b16 {%0,%1,%2,%3}, [%4];"
                 : "=r"(d0), "=r"(d1), "=r"(d2), "=r"(d3) : "r"(a));
}

__device__ __forceinline__ void ldsm4t(uint32_t& d0, uint32_t& d1, uint32_t& d2,
                                       uint32_t& d3, const bf16* p)
{
    uint32_t a = (uint32_t)__cvta_generic_to_shared(p);
    asm volatile("ldmatrix.sync.aligned.m8n8.x4.trans.shared.b16 {%0,%1,%2,%3}, [%4];"
                 : "=r"(d0), "=r"(d1), "=r"(d2), "=r"(d3) : "r"(a));
}

__device__ __forceinline__ void mma16816(float* c, const uint32_t* a,
                                         uint32_t b0, uint32_t b1)
{
    asm volatile(
        "mma.sync.aligned.m16n8k16.row.col.f32.bf16.bf16.f32 "
        "{%0,%1,%2,%3}, {%4,%5,%6,%7}, {%8,%9}, {%0,%1,%2,%3};"
        : "+f"(c[0]), "+f"(c[1]), "+f"(c[2]), "+f"(c[3])
        : "r"(a[0]), "r"(a[1]), "r"(a[2]), "r"(a[3]), "r"(b0), "r"(b1));
}

// ---------------------------------------------------------------------------
// bf16-pair tensor-core GEMM, fp32 accumulate, cp.async double-buffered.
//   C = alpha * (Ahi+Alo)(Bhi+Blo)^(T?)  (+bias)
// computed as Ahi*Bhi + Ahi*Blo + Alo*Bhi.
// A: M x K row-major. BT=true: B is N x K row-major (C=A*B^T).
//                     BT=false: B is K x N row-major (C=A*B).
// MODE 0: plain (B1 only).
// MODE 3: fused banded stage-4 (BT=false): k-tiles below diag use B2,
//         above use B1, the 4 diagonal tiles get two masked passes each.
// EPI 0: fp32 out (+optional col bias). EPI 1: bf16 hi/lo out (+col bias).
// ---------------------------------------------------------------------------
template <int MODE, bool BT, int EPI>
__global__ __launch_bounds__(256)
void mma_gemm(const bf16* __restrict__ Ah_, const bf16* __restrict__ Al_,
              const bf16* __restrict__ B1h_, const bf16* __restrict__ B1l_,
              const bf16* __restrict__ B2h_, const bf16* __restrict__ B2l_,
              const float* __restrict__ bias,
              float* __restrict__ Cf, bf16* __restrict__ Chi, bf16* __restrict__ Clo,
              int M, int N, int K, int lda, int ldb, int ldc,
              long sA, long sB, long sC, float alpha)
{
    extern __shared__ __align__(16) char dsm[];
    const uint32_t sbase = (uint32_t)__cvta_generic_to_shared(dsm);

    const bf16* Ah = Ah_ + (long)blockIdx.z * sA;
    const bf16* Al = Al_ + (long)blockIdx.z * sA;
    const bf16* B1h = B1h_ + (long)blockIdx.z * sB;
    const bf16* B1l = B1l_ + (long)blockIdx.z * sB;
    const bf16* B2h = (MODE == 3) ? B2h_ + (long)blockIdx.z * sB : nullptr;
    const bf16* B2l = (MODE == 3) ? B2l_ + (long)blockIdx.z * sB : nullptr;
    if (EPI == 0) Cf += (long)blockIdx.z * sC;
    else { Chi += (long)blockIdx.z * sC; Clo += (long)blockIdx.z * sC; }

    const int l0 = blockIdx.y * 128;
    const int n0 = blockIdx.x * 128;
    const int t = threadIdx.x;
    const int warp = t >> 5;
    const int lane = t & 31;
    const int wm = warp >> 2;        // 0..1
    const int wn = warp & 3;         // 0..3

    const int d0 = l0 >> 5;          // diagonal k-tile start (MODE 3)
    const int nt = (MODE == 3) ? (K / BK + 4) : (K / BK);

    float acc[4][4][4];
#pragma unroll
    for (int i = 0; i < 4; i++)
#pragma unroll
        for (int j = 0; j < 4; j++)
#pragma unroll
            for (int r = 0; r < 4; r++) acc[i][j][r] = 0.f;

    // --- issue loads for logical tile c into pipeline stage s ---
    auto issue_tile = [&](int c, int s) {
        int kt, mask;
        const bf16 *Bh, *Bl;
        if (MODE == 0) { kt = c * BK; Bh = B1h; Bl = B1l; mask = 0; }
        else {
            if (c < d0)            { kt = c * BK; Bh = B2h; Bl = B2l; mask = 0; }
            else if (c < d0 + 8)   { const int j = c - d0;
                                     kt = (d0 + (j >> 1)) * BK;
                                     if ((j & 1) == 0) { Bh = B1h; Bl = B1l; mask = 1; }
                                     else              { Bh = B2h; Bl = B2l; mask = 2; } }
            else                   { kt = (c - 4) * BK; Bh = B1h; Bl = B1l; mask = 0; }
        }
        const uint32_t aH = sbase + s * STG_B + OFF_AH;
        const uint32_t aL = sbase + s * STG_B + OFF_AL;
        const uint32_t bH = sbase + s * STG_B + OFF_BH;
        const uint32_t bL = sbase + s * STG_B + OFF_BL;

        // B tile
#pragma unroll
        for (int it = 0; it < 2; it++) {
            const int idx = t * 2 + it;
            if (BT) {      // 128 x 32, stride 40
                const int r = idx >> 2, c8 = (idx & 3) << 3;
                const long go = (long)(n0 + r) * ldb + kt + c8;
                const uint32_t so = (uint32_t)(r * 40 + c8) * 2;
                cpa16(bH + so, Bh + go);
                cpa16(bL + so, Bl + go);
            } else {       // 32 x 128, stride 136
                const int r = idx >> 4, c8 = (idx & 15) << 3;
                const long go = (long)(kt + r) * ldb + n0 + c8;
                const uint32_t so = (uint32_t)(r * 136 + c8) * 2;
                cpa16(bH + so, Bh + go);
                cpa16(bL + so, Bl + go);
            }
        }
        // A tile (128 x 32, stride 40)
        if (MODE == 0 || mask == 0) {
#pragma unroll
            for (int it = 0; it < 2; it++) {
                const int idx = t * 2 + it;
                const int r = idx >> 2, c8 = (idx & 3) << 3;
                const long go = (long)(l0 + r) * lda + kt + c8;
                const uint32_t so = (uint32_t)(r * 40 + c8) * 2;
                cpa16(aH + so, Ah + go);
                cpa16(aL + so, Al + go);
            }
        } else {
            // masked pairwise load for diagonal tiles
            const bf16 z = __float2bfloat16(0.f);
            bf16* pH = (bf16*)(dsm + s * STG_B + OFF_AH);
            bf16* pL = (bf16*)(dsm + s * STG_B + OFF_AL);
#pragma unroll
            for (int i = 0; i < 8; i++) {
                const int idx = t + i * 256;          // 0..2047
                const int r = idx >> 4, k2 = idx & 15;
                const int l = l0 + r;
                const int m0 = kt + 2 * k2;
                const long go = (long)l * lda + m0;
                __nv_bfloat162 vh = *(const __nv_bfloat162*)(Ah + go);
                __nv_bfloat162 vl = *(const __nv_bfloat162*)(Al + go);
                const bool k0 = (mask == 1) ? (m0 > l) : (m0 < l);
                const bool k1 = (mask == 1) ? (m0 + 1 > l) : (m0 + 1 < l);
                if (!k0) { vh.x = z; vl.x = z; }
                if (!k1) { vh.y = z; vl.y = z; }
                *(uint32_t*)(pH + r * 40 + 2 * k2) = *(uint32_t*)&vh;
                *(uint32_t*)(pL + r * 40 + 2 * k2) = *(uint32_t*)&vl;
            }
        }
        asm volatile("cp.async.commit_group;");
    };

    // --- compute one k-tile from pipeline stage s ---
    auto compute_tile = [&](int s) {
        const bf16* sAh = (const bf16*)(dsm + s * STG_B + OFF_AH);
        const bf16* sAl = (const bf16*)(dsm + s * STG_B + OFF_AL);
        const bf16* sBh = (const bf16*)(dsm + s * STG_B + OFF_BH);
        const bf16* sBl = (const bf16*)(dsm + s * STG_B + OFF_BL);
#pragma unroll
        for (int kk = 0; kk < 2; kk++) {
            uint32_t ah[4][4], al[4][4], bh[2][4], bl[2][4];
            const int arow = wm * 64 + (lane & 15);
            const int acol = kk * 16 + ((lane >> 4) << 3);
#pragma unroll
            for (int mi = 0; mi < 4; mi++) {
                ldsm4(ah[mi][0], ah[mi][1], ah[mi][2], ah[mi][3],
                      &sAh[(arow + mi * 16) * 40 + acol]);
                ldsm4(al[mi][0], al[mi][1], al[mi][2], al[mi][3],
                      &sAl[(arow + mi * 16) * 40 + acol]);
            }
            if (BT) {
                const int brow = wn * 32 + (lane & 15);
#pragma unroll
                for (int ni = 0; ni < 2; ni++) {
                    ldsm4(bh[ni][0], bh[ni][1], bh[ni][2], bh[ni][3],
                          &sBh[(brow + ni * 16) * 40 + acol]);
                    ldsm4(bl[ni][0], bl[ni][1], bl[ni][2], bl[ni][3],
                          &sBl[(brow + ni * 16) * 40 + acol]);
                }
            } else {
                const int krow = kk * 16 + (lane & 7) + ((lane >> 4) & 1) * 8;
                const int nc = wn * 32 + ((lane >> 3) & 1) * 8;
#pragma unroll
                for (int ni = 0; ni < 2; ni++) {
                    ldsm4t(bh[ni][0], bh[ni][1], bh[ni][2], bh[ni][3],
                           &sBh[krow * 136 + nc + ni * 16]);
                    ldsm4t(bl[ni][0], bl[ni][1], bl[ni][2], bl[ni][3],
                           &sBl[krow * 136 + nc + ni * 16]);
                }
            }
#pragma unroll
            for (int mi = 0; mi < 4; mi++)
#pragma unroll
                for (int j = 0; j < 4; j++) {
                    const int ni = j >> 1, hf = j & 1;
                    mma16816(acc[mi][j], ah[mi], bh[ni][hf], bh[ni][hf + 2]);
                    mma16816(acc[mi][j], ah[mi], bl[ni][hf], bl[ni][hf + 2]);
                    mma16816(acc[mi][j], al[mi], bh[ni][hf], bh[ni][hf + 2]);
                }
        }
    };

    // --- pipelined mainloop ---
    issue_tile(0, 0);
    for (int c = 0; c < nt; c++) {
        const int cur = c & 1;
        if (c + 1 < nt) {
            issue_tile(c + 1, cur ^ 1);
            asm volatile("cp.async.wait_group 1;" ::: "memory");
        } else {
            asm volatile("cp.async.wait_group 0;" ::: "memory");
        }
        __syncthreads();
        compute_tile(cur);
        __syncthreads();
    }

    // --- epilogue ---
    const int g = lane >> 2, tg = lane & 3;
#pragma unroll
    for (int mi = 0; mi < 4; mi++) {
#pragma unroll
        for (int j = 0; j < 4; j++) {
            const int gn = n0 + wn * 32 + j * 8 + tg * 2;
            const float* a = acc[mi][j];
#pragma unroll
            for (int h2 = 0; h2 < 2; h2++) {
                const int gm = l0 + wm * 64 + mi * 16 + g + h2 * 8;
                float v0 = a[h2 * 2 + 0] * alpha;
                float v1 = a[h2 * 2 + 1] * alpha;
                if (EPI == 0) {
                    if (bias) { v0 += bias[gn]; v1 += bias[gn + 1]; }
                    *(float2*)(Cf + (long)gm * ldc + gn) = make_float2(v0, v1);
                } else {
                    v0 += bias[gn]; v1 += bias[gn + 1];
                    bf16 h0, q0, h1, q1;
                    split_f32(v0, h0, q0);
                    split_f32(v1, h1, q1);
                    *(__nv_bfloat162*)(Chi + (long)gm * ldc + gn) = __halves2bfloat162(h0, h1);
                    *(__nv_bfloat162*)(Clo + (long)gm * ldc + gn) = __halves2bfloat162(q0, q1);
                }
            }
        }
    }
}

// ---------------------------------------------------------------------------
// fp32 -> bf16 hi/lo split (vectorized by 4)
// ---------------------------------------------------------------------------
__global__ __launch_bounds__(256)
void split4_kernel(const float* __restrict__ x, bf16* __restrict__ hi,
                   bf16* __restrict__ lo, long n4)
{
    const long i = (long)blockIdx.x * blockDim.x + threadIdx.x;
    if (i >= n4) return;
    float4 v = ((const float4*)x)[i];
    bf16 h0, l0, h1, l1, h2, l2, h3, l3;
    split_f32(v.x, h0, l0); split_f32(v.y, h1, l1);
    split_f32(v.z, h2, l2); split_f32(v.w, h3, l3);
    ((__nv_bfloat162*)hi)[i * 2 + 0] = __halves2bfloat162(h0, h1);
    ((__nv_bfloat162*)hi)[i * 2 + 1] = __halves2bfloat162(h2, h3);
    ((__nv_bfloat162*)lo)[i * 2 + 0] = __halves2bfloat162(l0, l1);
    ((__nv_bfloat162*)lo)[i * 2 + 1] = __halves2bfloat162(l2, l3);
}

// ---------------------------------------------------------------------------
// Block reductions (256 threads)
// ---------------------------------------------------------------------------
template <bool MAXOP>
__device__ __forceinline__ float block_reduce_256(float v)
{
    __shared__ float sm[8];
#pragma unroll
    for (int o = 16; o > 0; o >>= 1) {
        float w = __shfl_xor_sync(0xffffffffu, v, o);
        v = MAXOP ? fmaxf(v, w) : (v + w);
    }
    __syncthreads();
    if ((threadIdx.x & 31) == 0) sm[threadIdx.x >> 5] = v;
    __syncthreads();
    v = sm[threadIdx.x & 7];
#pragma unroll
    for (int o = 4; o > 0; o >>= 1) {
        float w = __shfl_xor_sync(0xffffffffu, v, o);
        v = MAXOP ? fmaxf(v, w) : (v + w);
    }
    return v;
}

// ---------------------------------------------------------------------------
// softmax + adjacency renorm:  attn = e*adj / (T + 1e-10*Z)
// ---------------------------------------------------------------------------
__global__ __launch_bounds__(256)
void softmax_adj_kernel(const float* __restrict__ S, const float* __restrict__ adj,
                        bf16* __restrict__ Shi, bf16* __restrict__ Slo,
                        float* __restrict__ diag)
{
    const int row = blockIdx.x;
    const int l = row & (LL - 1);
    const long base = (long)row * LL;
    const int t = threadIdx.x;

    float x[8], a[8];
#pragma unroll
    for (int i = 0; i < 8; i++) x[i] = S[base + t + i * 256];
#pragma unroll
    for (int i = 0; i < 8; i++) a[i] = adj[base + t + i * 256];

    float m = -INFINITY;
#pragma unroll
    for (int i = 0; i < 8; i++) m = fmaxf(m, x[i]);
    m = block_reduce_256<true>(m);

    float e[8];
    float z = 0.f, tt = 0.f;
#pragma unroll
    for (int i = 0; i < 8; i++) {
        e[i] = __expf(x[i] - m);
        z += e[i];
        tt += e[i] * a[i];
    }
    z  = block_reduce_256<false>(z);
    tt = block_reduce_256<false>(tt);

    const float inv = 1.0f / (tt + 1e-10f * z);
#pragma unroll
    for (int i = 0; i < 8; i++) {
        const int col = t + i * 256;
        const float v = e[i] * a[i] * inv;
        bf16 hi, lo;
        split_f32(v, hi, lo);
        Shi[base + col] = hi;
        Slo[base + col] = lo;
        if (col == l) diag[row] = v;
    }
}

// ---------------------------------------------------------------------------
// Fused: v = ctx + diag*h_self ; LayerNorm(eps=1e-12); ReLU
// ---------------------------------------------------------------------------
__global__ __launch_bounds__(256)
void ln_relu_kernel(const float* __restrict__ ctx, const float* __restrict__ HS,
                    const float* __restrict__ diag, const float* __restrict__ gamma,
                    const float* __restrict__ beta, float* __restrict__ out)
{
    const int row = blockIdx.x;
    const float a_ll = diag[row];
    const long rb = (long)row * HH;
    const int t = threadIdx.x;

    float v[3];
#pragma unroll
    for (int i = 0; i < 3; i++) {
        const int c = t + i * 256;
        v[i] = ctx[rb + c] + a_ll * HS[rb + c];
    }
    float s = v[0] + v[1] + v[2];
    s = block_reduce_256<false>(s);
    const float mu = s * (1.0f / HH);

    float sq = 0.f;
#pragma unroll
    for (int i = 0; i < 3; i++) {
        const float d = v[i] - mu;
        sq += d * d;
    }
    sq = block_reduce_256<false>(sq);
    const float rstd = rsqrtf(sq * (1.0f / HH) + 1e-12f);

#pragma unroll
    for (int i = 0; i < 3; i++) {
        const int c = t + i * 256;
        const float o = (v[i] - mu) * rstd * gamma[c] + beta[c];
        out[rb + c] = fmaxf(o, 0.f);
    }
}

// ---------------------------------------------------------------------------
extern "C" void kernel_launch(void* const* d_in, const int* in_sizes, int n_in,
                              void* d_out, int out_size)
{
    const float* h     = (const float*)d_in[0];
    const float* adj   = (const float*)d_in[1];
    const float* Wl    = (const float*)d_in[2];
    const float* bl    = (const float*)d_in[3];
    const float* Ws    = (const float*)d_in[4];
    const float* bs    = (const float*)d_in[5];
    const float* Wr    = (const float*)d_in[6];
    const float* br    = (const float*)d_in[7];
    const float* gamma = (const float*)d_in[8];
    const float* beta  = (const float*)d_in[9];
    float* out = (float*)d_out;

    float *S, *Pself, *CTX, *DIAG;
    bf16 *Shi, *Slo, *hhi, *hlo, *Whi, *Wlo, *PLhi, *PLlo, *PRhi, *PRlo;
    cudaGetSymbolAddress((void**)&S, g_S);
    cudaGetSymbolAddress((void**)&Shi, g_Shi);
    cudaGetSymbolAddress((void**)&Slo, g_Slo);
    cudaGetSymbolAddress((void**)&hhi, g_hhi);
    cudaGetSymbolAddress((void**)&hlo, g_hlo);
    cudaGetSymbolAddress((void**)&Whi, g_Whi);
    cudaGetSymbolAddress((void**)&Wlo, g_Wlo);
    cudaGetSymbolAddress((void**)&PLhi, g_PLhi);
    cudaGetSymbolAddress((void**)&PLlo, g_PLlo);
    cudaGetSymbolAddress((void**)&PRhi, g_PRhi);
    cudaGetSymbolAddress((void**)&PRlo, g_PRlo);
    cudaGetSymbolAddress((void**)&Pself, g_Pself);
    cudaGetSymbolAddress((void**)&CTX, g_ctx);
    cudaGetSymbolAddress((void**)&DIAG, g_diag);

    const long sLH = (long)LL * HH;
    const long sLL = (long)LL * LL;
    const long WW = (long)HH * HH;
    const int BL = BB * LL;  // 16384
    const float inv_sqrt_h = 1.0f / sqrtf((float)HH);

    cudaFuncSetAttribute(mma_gemm<0, true, 0>,
                         cudaFuncAttributeMaxDynamicSharedMemorySize, DSMEM_BYTES);
    cudaFuncSetAttribute(mma_gemm<0, true, 1>,
                         cudaFuncAttributeMaxDynamicSharedMemorySize, DSMEM_BYTES);
    cudaFuncSetAttribute(mma_gemm<3, false, 0>,
                         cudaFuncAttributeMaxDynamicSharedMemorySize, DSMEM_BYTES);

    // 0) operand conversion
    {
        const long n4h = (long)BL * HH / 4;
        split4_kernel<<<(int)((n4h + 255) / 256), 256>>>(h, hhi, hlo, n4h);
        const long n4w = WW / 4;
        split4_kernel<<<(int)((n4w + 255) / 256), 256>>>(Wl, Whi + 0 * WW, Wlo + 0 * WW, n4w);
        split4_kernel<<<(int)((n4w + 255) / 256), 256>>>(Ws, Whi + 1 * WW, Wlo + 1 * WW, n4w);
        split4_kernel<<<(int)((n4w + 255) / 256), 256>>>(Wr, Whi + 2 * WW, Wlo + 2 * WW, n4w);
    }

    // 1) S = h @ h^T / sqrt(H)  (NT, batched)
    {
        dim3 grid(LL / 128, LL / 128, BB);
        mma_gemm<0, true, 0><<<grid, 256, DSMEM_BYTES>>>(
            hhi, hlo, hhi, hlo, nullptr, nullptr, nullptr,
            S, nullptr, nullptr,
            LL, LL, HH, HH, HH, LL, sLH, sLH, sLL, inv_sqrt_h);
    }

    // 2) softmax + adjacency renorm -> attn pair + diag
    softmax_adj_kernel<<<BB * LL, 256>>>(S, adj, Shi, Slo, DIAG);

    // 3) projections (NT, M = B*L): PL/PR as bf16 pair, h_self fp32
    {
        dim3 grid(HH / 128, BL / 128, 1);
        mma_gemm<0, true, 1><<<grid, 256, DSMEM_BYTES>>>(
            hhi, hlo, Whi + 0 * WW, Wlo + 0 * WW, nullptr, nullptr, bl,
            nullptr, PLhi, PLlo,
            BL, HH, HH, HH, HH, HH, 0, 0, 0, 1.f);
        mma_gemm<0, true, 1><<<grid, 256, DSMEM_BYTES>>>(
            hhi, hlo, Whi + 2 * WW, Wlo + 2 * WW, nullptr, nullptr, br,
            nullptr, PRhi, PRlo,
            BL, HH, HH, HH, HH, HH, 0, 0, 0, 1.f);
        mma_gemm<0, true, 0><<<grid, 256, DSMEM_BYTES>>>(
            hhi, hlo, Whi + 1 * WW, Wlo + 1 * WW, nullptr, nullptr, bs,
            Pself, nullptr, nullptr,
            BL, HH, HH, HH, HH, HH, 0, 0, 0, 1.f);
    }

    // 4) ctx = triu(attn,1) @ PL + tril(attn,-1) @ PR  (fused banded, batched)
    {
        dim3 grid(HH / 128, LL / 128, BB);
        mma_gemm<3, false, 0><<<grid, 256, DSMEM_BYTES>>>(
            Shi, Slo, PLhi, PLlo, PRhi, PRlo, nullptr,
            CTX, nullptr, nullptr,
            LL, HH, LL, LL, HH, HH, sLL, sLH, sLH, 1.f);
    }

    // 5) + diag*h_self, LayerNorm, ReLU
    ln_relu_kernel<<<BB * LL, 256>>>(CTX, Pself, DIAG, gamma, beta, out);
}

// round 10
// speedup vs baseline: 3.0210x; 1.3391x over previous
#include <cuda_runtime.h>
#include <cuda_fp16.h>
#include <math.h>
#include <stdint.h>

// Problem constants
#define BB 8
#define LL 2048
#define HH 768

typedef __half f16;

// Tiling: CTA 128x128, 8 warps (2x4), warp 64x32, k-tile 32, 2-stage pipeline
#define BK 32
#define STG_B 30720          // bytes per stage: AH | AL | BH (3 x 10240)
#define OFF_AH 0
#define OFF_AL 10240
#define OFF_BH 20480
#define DSMEM_BYTES (2 * STG_B)

// ---------------------------------------------------------------------------
// Static scratch (allocation-free per harness rules)
// ---------------------------------------------------------------------------
__device__ float g_S   [(long)BB * LL * LL];     // fp32 scores
__device__ f16   g_Shi [(long)BB * LL * LL];     // attn hi
__device__ f16   g_Slo [(long)BB * LL * LL];     // attn lo
__device__ f16   g_hhi [(long)BB * LL * HH];
__device__ f16   g_hlo [(long)BB * LL * HH];
__device__ f16   g_Wh  [3L * HH * HH];           // fp16(Wl|Ws|Wr)
__device__ f16   g_PL  [(long)BB * LL * HH];     // h_left  fp16 [bL][e]
__device__ f16   g_PR  [(long)BB * LL * HH];     // h_right fp16
__device__ float g_Pself[(long)BB * LL * HH];    // h_self fp32
__device__ float g_ctx [(long)BB * LL * HH];
__device__ float g_diag[(long)BB * LL];

// ---------------------------------------------------------------------------
// Helpers
// ---------------------------------------------------------------------------
__device__ __forceinline__ void split_f32(float x, f16& hi, f16& lo)
{
    hi = __float2half_rn(x);
    lo = __float2half_rn(x - __half2float(hi));
}

__device__ __forceinline__ void cpa16(uint32_t dst, const void* src)
{
    asm volatile("cp.async.cg.shared.global [%0], [%1], 16;" :: "r"(dst), "l"(src));
}

__device__ __forceinline__ void ldsm4(uint32_t& d0, uint32_t& d1, uint32_t& d2,
                                      uint32_t& d3, const f16* p)
{
    uint32_t a = (uint32_t)__cvta_generic_to_shared(p);
    asm volatile("ldmatrix.sync.aligned.m8n8.x4.shared.b16 {%0,%1,%2,%3}, [%4];"
                 : "=r"(d0), "=r"(d1), "=r"(d2), "=r"(d3) : "r"(a));
}

__device__ __forceinline__ void ldsm4t(uint32_t& d0, uint32_t& d1, uint32_t& d2,
                                       uint32_t& d3, const f16* p)
{
    uint32_t a = (uint32_t)__cvta_generic_to_shared(p);
    asm volatile("ldmatrix.sync.aligned.m8n8.x4.trans.shared.b16 {%0,%1,%2,%3}, [%4];"
                 : "=r"(d0), "=r"(d1), "=r"(d2), "=r"(d3) : "r"(a));
}

__device__ __forceinline__ void mma16816(float* c, const uint32_t* a,
                                         uint32_t b0, uint32_t b1)
{
    asm volatile(
        "mma.sync.aligned.m16n8k16.row.col.f32.f16.f16.f32 "
        "{%0,%1,%2,%3}, {%4,%5,%6,%7}, {%8,%9}, {%0,%1,%2,%3};"
        : "+f"(c[0]), "+f"(c[1]), "+f"(c[2]), "+f"(c[3])
        : "r"(a[0]), "r"(a[1]), "r"(a[2]), "r"(a[3]), "r"(b0), "r"(b1));
}

// ---------------------------------------------------------------------------
// fp16 2-product tensor-core GEMM, fp32 accumulate, cp.async double-buffered.
//   C = alpha * (Ahi + Alo) * B^(T?)   (+bias)       [B already fp16]
// MMA count: 2 per (mi,j) vs 3 for bf16-3P — the legacy HMMA pipe (rt~16)
// is the bottleneck, so MMA count is the cost model.
// A: M x K row-major (hi/lo pair). BT=true: B is N x K (C=A*B^T).
//                                  BT=false: B is K x N (C=A*B).
// MODE 0: plain (B1 only).
// MODE 3: fused banded stage-4 (BT=false): k-tiles below diag use B2,
//         above use B1, the 4 diagonal tiles get two masked passes each.
// EPI 0: fp32 out (+optional col bias). EPI 1: fp16 out (+col bias).
// ---------------------------------------------------------------------------
template <int MODE, bool BT, int EPI>
__global__ __launch_bounds__(256)
void mma_gemm(const f16* __restrict__ Ah_, const f16* __restrict__ Al_,
              const f16* __restrict__ B1_, const f16* __restrict__ B2_,
              const float* __restrict__ bias,
              float* __restrict__ Cf, f16* __restrict__ Ch,
              int M, int N, int K, int lda, int ldb, int ldc,
              long sA, long sB, long sC, float alpha)
{
    extern __shared__ __align__(16) char dsm[];
    const uint32_t sbase = (uint32_t)__cvta_generic_to_shared(dsm);

    const f16* Ah = Ah_ + (long)blockIdx.z * sA;
    const f16* Al = Al_ + (long)blockIdx.z * sA;
    const f16* B1 = B1_ + (long)blockIdx.z * sB;
    const f16* B2 = (MODE == 3) ? B2_ + (long)blockIdx.z * sB : nullptr;
    if (EPI == 0) Cf += (long)blockIdx.z * sC;
    else          Ch += (long)blockIdx.z * sC;

    const int l0 = blockIdx.y * 128;
    const int n0 = blockIdx.x * 128;
    const int t = threadIdx.x;
    const int warp = t >> 5;
    const int lane = t & 31;
    const int wm = warp >> 2;        // 0..1
    const int wn = warp & 3;         // 0..3

    const int d0 = l0 >> 5;          // diagonal k-tile start (MODE 3)
    const int nt = (MODE == 3) ? (K / BK + 4) : (K / BK);

    float acc[4][4][4];
#pragma unroll
    for (int i = 0; i < 4; i++)
#pragma unroll
        for (int j = 0; j < 4; j++)
#pragma unroll
            for (int r = 0; r < 4; r++) acc[i][j][r] = 0.f;

    // --- issue loads for logical tile c into pipeline stage s ---
    auto issue_tile = [&](int c, int s) {
        int kt, mask;
        const f16* Bp;
        if (MODE == 0) { kt = c * BK; Bp = B1; mask = 0; }
        else {
            if (c < d0)            { kt = c * BK; Bp = B2; mask = 0; }
            else if (c < d0 + 8)   { const int j = c - d0;
                                     kt = (d0 + (j >> 1)) * BK;
                                     if ((j & 1) == 0) { Bp = B1; mask = 1; }
                                     else              { Bp = B2; mask = 2; } }
            else                   { kt = (c - 4) * BK; Bp = B1; mask = 0; }
        }
        const uint32_t aH = sbase + s * STG_B + OFF_AH;
        const uint32_t aL = sbase + s * STG_B + OFF_AL;
        const uint32_t bH = sbase + s * STG_B + OFF_BH;

        // B tile (hi only): 512 x 16B chunks
#pragma unroll
        for (int it = 0; it < 2; it++) {
            const int idx = t * 2 + it;
            if (BT) {      // 128 x 32, stride 40
                const int r = idx >> 2, c8 = (idx & 3) << 3;
                const long go = (long)(n0 + r) * ldb + kt + c8;
                cpa16(bH + (uint32_t)(r * 40 + c8) * 2, Bp + go);
            } else {       // 32 x 128, stride 136
                const int r = idx >> 4, c8 = (idx & 15) << 3;
                const long go = (long)(kt + r) * ldb + n0 + c8;
                cpa16(bH + (uint32_t)(r * 136 + c8) * 2, Bp + go);
            }
        }
        // A tile hi+lo (128 x 32, stride 40)
        if (MODE == 0 || mask == 0) {
#pragma unroll
            for (int it = 0; it < 2; it++) {
                const int idx = t * 2 + it;
                const int r = idx >> 2, c8 = (idx & 3) << 3;
                const long go = (long)(l0 + r) * lda + kt + c8;
                const uint32_t so = (uint32_t)(r * 40 + c8) * 2;
                cpa16(aH + so, Ah + go);
                cpa16(aL + so, Al + go);
            }
        } else {
            // masked pairwise load for diagonal tiles
            const f16 z = __float2half_rn(0.f);
            f16* pH = (f16*)(dsm + s * STG_B + OFF_AH);
            f16* pL = (f16*)(dsm + s * STG_B + OFF_AL);
#pragma unroll
            for (int i = 0; i < 8; i++) {
                const int idx = t + i * 256;          // 0..2047
                const int r = idx >> 4, k2 = idx & 15;
                const int l = l0 + r;
                const int m0 = kt + 2 * k2;
                const long go = (long)l * lda + m0;
                __half2 vh = *(const __half2*)(Ah + go);
                __half2 vl = *(const __half2*)(Al + go);
                const bool k0 = (mask == 1) ? (m0 > l) : (m0 < l);
                const bool k1 = (mask == 1) ? (m0 + 1 > l) : (m0 + 1 < l);
                if (!k0) { vh.x = z; vl.x = z; }
                if (!k1) { vh.y = z; vl.y = z; }
                *(uint32_t*)(pH + r * 40 + 2 * k2) = *(uint32_t*)&vh;
                *(uint32_t*)(pL + r * 40 + 2 * k2) = *(uint32_t*)&vl;
            }
        }
        asm volatile("cp.async.commit_group;");
    };

    // --- compute one k-tile from pipeline stage s ---
    auto compute_tile = [&](int s) {
        const f16* sAh = (const f16*)(dsm + s * STG_B + OFF_AH);
        const f16* sAl = (const f16*)(dsm + s * STG_B + OFF_AL);
        const f16* sBh = (const f16*)(dsm + s * STG_B + OFF_BH);
#pragma unroll
        for (int kk = 0; kk < 2; kk++) {
            uint32_t ah[4][4], al[4][4], bh[2][4];
            const int arow = wm * 64 + (lane & 15);
            const int acol = kk * 16 + ((lane >> 4) << 3);
#pragma unroll
            for (int mi = 0; mi < 4; mi++) {
                ldsm4(ah[mi][0], ah[mi][1], ah[mi][2], ah[mi][3],
                      &sAh[(arow + mi * 16) * 40 + acol]);
                ldsm4(al[mi][0], al[mi][1], al[mi][2], al[mi][3],
                      &sAl[(arow + mi * 16) * 40 + acol]);
            }
            if (BT) {
                const int brow = wn * 32 + (lane & 15);
#pragma unroll
                for (int ni = 0; ni < 2; ni++)
                    ldsm4(bh[ni][0], bh[ni][1], bh[ni][2], bh[ni][3],
                          &sBh[(brow + ni * 16) * 40 + acol]);
            } else {
                const int krow = kk * 16 + (lane & 7) + ((lane >> 4) & 1) * 8;
                const int nc = wn * 32 + ((lane >> 3) & 1) * 8;
#pragma unroll
                for (int ni = 0; ni < 2; ni++)
                    ldsm4t(bh[ni][0], bh[ni][1], bh[ni][2], bh[ni][3],
                           &sBh[krow * 136 + nc + ni * 16]);
            }
#pragma unroll
            for (int mi = 0; mi < 4; mi++)
#pragma unroll
                for (int j = 0; j < 4; j++) {
                    const int ni = j >> 1, hf = j & 1;
                    mma16816(acc[mi][j], ah[mi], bh[ni][hf], bh[ni][hf + 2]);
                    mma16816(acc[mi][j], al[mi], bh[ni][hf], bh[ni][hf + 2]);
                }
        }
    };

    // --- pipelined mainloop ---
    issue_tile(0, 0);
    for (int c = 0; c < nt; c++) {
        const int cur = c & 1;
        if (c + 1 < nt) {
            issue_tile(c + 1, cur ^ 1);
            asm volatile("cp.async.wait_group 1;" ::: "memory");
        } else {
            asm volatile("cp.async.wait_group 0;" ::: "memory");
        }
        __syncthreads();
        compute_tile(cur);
        __syncthreads();
    }

    // --- epilogue ---
    const int g = lane >> 2, tg = lane & 3;
#pragma unroll
    for (int mi = 0; mi < 4; mi++) {
#pragma unroll
        for (int j = 0; j < 4; j++) {
            const int gn = n0 + wn * 32 + j * 8 + tg * 2;
            const float* a = acc[mi][j];
#pragma unroll
            for (int h2 = 0; h2 < 2; h2++) {
                const int gm = l0 + wm * 64 + mi * 16 + g + h2 * 8;
                float v0 = a[h2 * 2 + 0] * alpha;
                float v1 = a[h2 * 2 + 1] * alpha;
                if (EPI == 0) {
                    if (bias) { v0 += bias[gn]; v1 += bias[gn + 1]; }
                    *(float2*)(Cf + (long)gm * ldc + gn) = make_float2(v0, v1);
                } else {
                    v0 += bias[gn]; v1 += bias[gn + 1];
                    *(__half2*)(Ch + (long)gm * ldc + gn) =
                        __halves2half2(__float2half_rn(v0), __float2half_rn(v1));
                }
            }
        }
    }
}

// ---------------------------------------------------------------------------
// fp32 -> fp16 hi/lo split (vectorized by 4)
// ---------------------------------------------------------------------------
__global__ __launch_bounds__(256)
void split4_kernel(const float* __restrict__ x, f16* __restrict__ hi,
                   f16* __restrict__ lo, long n4)
{
    const long i = (long)blockIdx.x * blockDim.x + threadIdx.x;
    if (i >= n4) return;
    float4 v = ((const float4*)x)[i];
    f16 h0, l0, h1, l1, h2, l2, h3, l3;
    split_f32(v.x, h0, l0); split_f32(v.y, h1, l1);
    split_f32(v.z, h2, l2); split_f32(v.w, h3, l3);
    ((__half2*)hi)[i * 2 + 0] = __halves2half2(h0, h1);
    ((__half2*)hi)[i * 2 + 1] = __halves2half2(h2, h3);
    ((__half2*)lo)[i * 2 + 0] = __halves2half2(l0, l1);
    ((__half2*)lo)[i * 2 + 1] = __halves2half2(l2, l3);
}

// fp32 -> fp16 convert only (for weights; residual dropped by 2-product scheme)
__global__ __launch_bounds__(256)
void cvt4_kernel(const float* __restrict__ x, f16* __restrict__ y, long n4)
{
    const long i = (long)blockIdx.x * blockDim.x + threadIdx.x;
    if (i >= n4) return;
    float4 v = ((const float4*)x)[i];
    ((__half2*)y)[i * 2 + 0] = __halves2half2(__float2half_rn(v.x), __float2half_rn(v.y));
    ((__half2*)y)[i * 2 + 1] = __halves2half2(__float2half_rn(v.z), __float2half_rn(v.w));
}

// ---------------------------------------------------------------------------
// Block reductions (256 threads)
// ---------------------------------------------------------------------------
template <bool MAXOP>
__device__ __forceinline__ float block_reduce_256(float v)
{
    __shared__ float sm[8];
#pragma unroll
    for (int o = 16; o > 0; o >>= 1) {
        float w = __shfl_xor_sync(0xffffffffu, v, o);
        v = MAXOP ? fmaxf(v, w) : (v + w);
    }
    __syncthreads();
    if ((threadIdx.x & 31) == 0) sm[threadIdx.x >> 5] = v;
    __syncthreads();
    v = sm[threadIdx.x & 7];
#pragma unroll
    for (int o = 4; o > 0; o >>= 1) {
        float w = __shfl_xor_sync(0xffffffffu, v, o);
        v = MAXOP ? fmaxf(v, w) : (v + w);
    }
    return v;
}

// ---------------------------------------------------------------------------
// softmax + adjacency renorm:  attn = e*adj / (T + 1e-10*Z)
// ---------------------------------------------------------------------------
__global__ __launch_bounds__(256)
void softmax_adj_kernel(const float* __restrict__ S, const float* __restrict__ adj,
                        f16* __restrict__ Shi, f16* __restrict__ Slo,
                        float* __restrict__ diag)
{
    const int row = blockIdx.x;
    const int l = row & (LL - 1);
    const long base = (long)row * LL;
    const int t = threadIdx.x;

    float x[8], a[8];
#pragma unroll
    for (int i = 0; i < 8; i++) x[i] = S[base + t + i * 256];
#pragma unroll
    for (int i = 0; i < 8; i++) a[i] = adj[base + t + i * 256];

    float m = -INFINITY;
#pragma unroll
    for (int i = 0; i < 8; i++) m = fmaxf(m, x[i]);
    m = block_reduce_256<true>(m);

    float e[8];
    float z = 0.f, tt = 0.f;
#pragma unroll
    for (int i = 0; i < 8; i++) {
        e[i] = __expf(x[i] - m);
        z += e[i];
        tt += e[i] * a[i];
    }
    z  = block_reduce_256<false>(z);
    tt = block_reduce_256<false>(tt);

    const float inv = 1.0f / (tt + 1e-10f * z);
#pragma unroll
    for (int i = 0; i < 8; i++) {
        const int col = t + i * 256;
        const float v = e[i] * a[i] * inv;
        f16 hi, lo;
        split_f32(v, hi, lo);
        Shi[base + col] = hi;
        Slo[base + col] = lo;
        if (col == l) diag[row] = v;
    }
}

// ---------------------------------------------------------------------------
// Fused: v = ctx + diag*h_self ; LayerNorm(eps=1e-12); ReLU
// ---------------------------------------------------------------------------
__global__ __launch_bounds__(256)
void ln_relu_kernel(const float* __restrict__ ctx, const float* __restrict__ HS,
                    const float* __restrict__ diag, const float* __restrict__ gamma,
                    const float* __restrict__ beta, float* __restrict__ out)
{
    const int row = blockIdx.x;
    const float a_ll = diag[row];
    const long rb = (long)row * HH;
    const int t = threadIdx.x;

    float v[3];
#pragma unroll
    for (int i = 0; i < 3; i++) {
        const int c = t + i * 256;
        v[i] = ctx[rb + c] + a_ll * HS[rb + c];
    }
    float s = v[0] + v[1] + v[2];
    s = block_reduce_256<false>(s);
    const float mu = s * (1.0f / HH);

    float sq = 0.f;
#pragma unroll
    for (int i = 0; i < 3; i++) {
        const float d = v[i] - mu;
        sq += d * d;
    }
    sq = block_reduce_256<false>(sq);
    const float rstd = rsqrtf(sq * (1.0f / HH) + 1e-12f);

#pragma unroll
    for (int i = 0; i < 3; i++) {
        const int c = t + i * 256;
        const float o = (v[i] - mu) * rstd * gamma[c] + beta[c];
        out[rb + c] = fmaxf(o, 0.f);
    }
}

// ---------------------------------------------------------------------------
extern "C" void kernel_launch(void* const* d_in, const int* in_sizes, int n_in,
                              void* d_out, int out_size)
{
    const float* h     = (const float*)d_in[0];
    const float* adj   = (const float*)d_in[1];
    const float* Wl    = (const float*)d_in[2];
    const float* bl    = (const float*)d_in[3];
    const float* Ws    = (const float*)d_in[4];
    const float* bs    = (const float*)d_in[5];
    const float* Wr    = (const float*)d_in[6];
    const float* br    = (const float*)d_in[7];
    const float* gamma = (const float*)d_in[8];
    const float* beta  = (const float*)d_in[9];
    float* out = (float*)d_out;

    float *S, *Pself, *CTX, *DIAG;
    f16 *Shi, *Slo, *hhi, *hlo, *Wh, *PL, *PR;
    cudaGetSymbolAddress((void**)&S, g_S);
    cudaGetSymbolAddress((void**)&Shi, g_Shi);
    cudaGetSymbolAddress((void**)&Slo, g_Slo);
    cudaGetSymbolAddress((void**)&hhi, g_hhi);
    cudaGetSymbolAddress((void**)&hlo, g_hlo);
    cudaGetSymbolAddress((void**)&Wh, g_Wh);
    cudaGetSymbolAddress((void**)&PL, g_PL);
    cudaGetSymbolAddress((void**)&PR, g_PR);
    cudaGetSymbolAddress((void**)&Pself, g_Pself);
    cudaGetSymbolAddress((void**)&CTX, g_ctx);
    cudaGetSymbolAddress((void**)&DIAG, g_diag);

    const long sLH = (long)LL * HH;
    const long sLL = (long)LL * LL;
    const long WW = (long)HH * HH;
    const int BL = BB * LL;  // 16384
    const float inv_sqrt_h = 1.0f / sqrtf((float)HH);

    cudaFuncSetAttribute(mma_gemm<0, true, 0>,
                         cudaFuncAttributeMaxDynamicSharedMemorySize, DSMEM_BYTES);
    cudaFuncSetAttribute(mma_gemm<0, true, 1>,
                         cudaFuncAttributeMaxDynamicSharedMemorySize, DSMEM_BYTES);
    cudaFuncSetAttribute(mma_gemm<3, false, 0>,
                         cudaFuncAttributeMaxDynamicSharedMemorySize, DSMEM_BYTES);

    // 0) operand conversion
    {
        const long n4h = (long)BL * HH / 4;
        split4_kernel<<<(int)((n4h + 255) / 256), 256>>>(h, hhi, hlo, n4h);
        const long n4w = WW / 4;
        cvt4_kernel<<<(int)((n4w + 255) / 256), 256>>>(Wl, Wh + 0 * WW, n4w);
        cvt4_kernel<<<(int)((n4w + 255) / 256), 256>>>(Ws, Wh + 1 * WW, n4w);
        cvt4_kernel<<<(int)((n4w + 255) / 256), 256>>>(Wr, Wh + 2 * WW, n4w);
    }

    // 1) S = h @ h^T / sqrt(H)  (NT, batched): (hhi+hlo) @ hhi^T
    {
        dim3 grid(LL / 128, LL / 128, BB);
        mma_gemm<0, true, 0><<<grid, 256, DSMEM_BYTES>>>(
            hhi, hlo, hhi, nullptr, nullptr,
            S, nullptr,
            LL, LL, HH, HH, HH, LL, sLH, sLH, sLL, inv_sqrt_h);
    }

    // 2) softmax + adjacency renorm -> attn pair + diag
    softmax_adj_kernel<<<BB * LL, 256>>>(S, adj, Shi, Slo, DIAG);

    // 3) projections (NT, M = B*L): PL/PR fp16, h_self fp32
    {
        dim3 grid(HH / 128, BL / 128, 1);
        mma_gemm<0, true, 1><<<grid, 256, DSMEM_BYTES>>>(
            hhi, hlo, Wh + 0 * WW, nullptr, bl,
            nullptr, PL,
            BL, HH, HH, HH, HH, HH, 0, 0, 0, 1.f);
        mma_gemm<0, true, 1><<<grid, 256, DSMEM_BYTES>>>(
            hhi, hlo, Wh + 2 * WW, nullptr, br,
            nullptr, PR,
            BL, HH, HH, HH, HH, HH, 0, 0, 0, 1.f);
        mma_gemm<0, true, 0><<<grid, 256, DSMEM_BYTES>>>(
            hhi, hlo, Wh + 1 * WW, nullptr, bs,
            Pself, nullptr,
            BL, HH, HH, HH, HH, HH, 0, 0, 0, 1.f);
    }

    // 4) ctx = triu(attn,1) @ PL + tril(attn,-1) @ PR  (fused banded, batched)
    {
        dim3 grid(HH / 128, LL / 128, BB);
        mma_gemm<3, false, 0><<<grid, 256, DSMEM_BYTES>>>(
            Shi, Slo, PL, PR, nullptr,
            CTX, nullptr,
            LL, HH, LL, LL, HH, HH, sLL, sLH, sLH, 1.f);
    }

    // 5) + diag*h_self, LayerNorm, ReLU
    ln_relu_kernel<<<BB * LL, 256>>>(CTX, Pself, DIAG, gamma, beta, out);
}